// round 15
// baseline (speedup 1.0000x reference)
#include <cuda_runtime.h>
#include <cuda_fp16.h>
#include <math.h>
#include <stdint.h>

#define DM   1024
#define NH   16
#define HD   64
#define NB   2
#define SL   2048
#define MT   (NB*SL)   // 4096

// fp16 scratch (device globals: allocation-free)
__device__ __align__(16) __half g_xh[MT*DM];
__device__ __align__(16) __half g_wqh[DM*DM];
__device__ __align__(16) __half g_wkh[DM*DM];
__device__ __align__(16) __half g_wvh[DM*DM];
__device__ __align__(16) __half g_woh[DM*DM];
__device__ __align__(16) __half g_qh[NB*NH*SL*HD];   // [B][H][L][Dh], pre-scaled by log2e/8
__device__ __align__(16) __half g_kh[NB*NH*SL*HD];
__device__ __align__(16) __half g_vh[NB*NH*SL*HD];
__device__ __align__(16) __half g_ah[MT*DM];         // attn out [B,L,D]
__device__ float g_cos[SL*32];
__device__ float g_sin[SL*32];

// ---------------- helpers ----------------
__device__ __forceinline__ uint32_t saddr(const void* p) {
    return (uint32_t)__cvta_generic_to_shared(p);
}
__device__ __forceinline__ void ldsm4(uint32_t& r0, uint32_t& r1, uint32_t& r2, uint32_t& r3, uint32_t a) {
    asm volatile("ldmatrix.sync.aligned.m8n8.x4.shared.b16 {%0,%1,%2,%3}, [%4];"
        : "=r"(r0), "=r"(r1), "=r"(r2), "=r"(r3) : "r"(a));
}
__device__ __forceinline__ void ldsm4t(uint32_t& r0, uint32_t& r1, uint32_t& r2, uint32_t& r3, uint32_t a) {
    asm volatile("ldmatrix.sync.aligned.m8n8.x4.trans.shared.b16 {%0,%1,%2,%3}, [%4];"
        : "=r"(r0), "=r"(r1), "=r"(r2), "=r"(r3) : "r"(a));
}
__device__ __forceinline__ void mma16816(float* c, const uint32_t* a, const uint32_t* b) {
    asm volatile("mma.sync.aligned.m16n8k16.row.col.f32.f16.f16.f32 "
        "{%0,%1,%2,%3}, {%4,%5,%6,%7}, {%8,%9}, {%0,%1,%2,%3};"
        : "+f"(c[0]), "+f"(c[1]), "+f"(c[2]), "+f"(c[3])
        : "r"(a[0]), "r"(a[1]), "r"(a[2]), "r"(a[3]), "r"(b[0]), "r"(b[1]));
}
// fp16-accumulate variant (2x rate): C/D are 2 regs of f16x2.
__device__ __forceinline__ void mma16816h(uint32_t* c, const uint32_t* a, const uint32_t* b) {
    asm volatile("mma.sync.aligned.m16n8k16.row.col.f16.f16.f16.f16 "
        "{%0,%1}, {%2,%3,%4,%5}, {%6,%7}, {%0,%1};"
        : "+r"(c[0]), "+r"(c[1])
        : "r"(a[0]), "r"(a[1]), "r"(a[2]), "r"(a[3]), "r"(b[0]), "r"(b[1]));
}
__device__ __forceinline__ uint32_t pack_h2(float a, float b) {
    __half2 h = __floats2half2_rn(a, b);
    return *reinterpret_cast<uint32_t*>(&h);
}
// ex2 on an f16x2 register (log2-domain -> probabilities), one MUFU for 2 elems
__device__ __forceinline__ uint32_t exp2_h2r(uint32_t p) {
    uint32_t r;
    asm volatile("ex2.approx.f16x2 %0, %1;" : "=r"(r) : "r"(p));
    return r;
}
__device__ __forceinline__ void cpa16(uint32_t dst, const void* src) {
    asm volatile("cp.async.cg.shared.global [%0], [%1], 16;" :: "r"(dst), "l"(src));
}
#define CP_COMMIT() asm volatile("cp.async.commit_group;")
#define CP_WAIT(n)  asm volatile("cp.async.wait_group %0;" :: "n"(n))

// XOR-swizzled byte offset inside a [rows][64 halves] tile (128B row pitch)
__device__ __forceinline__ uint32_t sw(int r, int c8) {
    return (uint32_t)(r * 128 + ((c8 ^ (r & 7)) << 4));
}

#define QSCALE 0.18033688011112042f   // log2(e)/8

// ---------------- merged prepass: 5x f2h + rope table, one launch ----------
__global__ __launch_bounds__(256)
void prepass(const float* __restrict__ x,
             const float* __restrict__ Wq, const float* __restrict__ Wk,
             const float* __restrict__ Wv, const float* __restrict__ Wo)
{
    int b = blockIdx.x;
    if (b >= 2048) {   // rope: 65536 elems, 64 blocks x 256 thr x 4
        int i0 = (b - 2048) * 1024 + threadIdx.x;
        #pragma unroll
        for (int u = 0; u < 4; u++) {
            int i = i0 + u * 256;
            int l = i >> 5, j = i & 31;
            float inv = (float)exp((double)j * -0.28782313662425572);  // 10000^(-j/32)
            float ang = (float)l * inv;
            float s, c;
            sincosf(ang, &s, &c);
            g_cos[i] = c;
            g_sin[i] = s;
        }
        return;
    }
    const float* src;
    __half* dst;
    int base;
    if      (b < 1024) { src = x;  dst = g_xh;  base = 0;    }
    else if (b < 1280) { src = Wq; dst = g_wqh; base = 1024; }
    else if (b < 1536) { src = Wk; dst = g_wkh; base = 1280; }
    else if (b < 1792) { src = Wv; dst = g_wvh; base = 1536; }
    else               { src = Wo; dst = g_woh; base = 1792; }
    int i0 = (b - base) * 1024 + threadIdx.x;
    #pragma unroll
    for (int u = 0; u < 4; u++) {
        int i = i0 + u * 256;
        float4 v = ((const float4*)src)[i];
        uint2 h;
        h.x = pack_h2(v.x, v.y);
        h.y = pack_h2(v.z, v.w);
        ((uint2*)dst)[i] = h;
    }
}

// ============================================================================
// GEMM body (fp16 in): out[m,n] = sum_k A[m,k]*B[n,k] + bias[n].
// CTA 128x128, 8 warps (4m x 2n), k-slice 64, 3-stage cp.async pipeline.
// (Round-13 shape — the round-14 128-thr reshape regressed and was reverted.)
// ============================================================================
__device__ __forceinline__
void gemm_body(const __half* __restrict__ A, const __half* __restrict__ B,
               const float* __restrict__ bias, void* __restrict__ outp,
               int mode, float postscale, uint32_t sb, int m0, int n0)
{
    const int tid = threadIdx.x, lane = tid & 31, warp = tid >> 5;
    const int wm = warp >> 1, wn = warp & 1;
    const int nb = n0 + wn * 64;

    auto issue = [&](int st, int ko) {
        uint32_t ab = sb + st * 32768;
        uint32_t bb = ab + 16384;
        #pragma unroll
        for (int u = 0; u < 4; u++) {
            int i = tid + 256 * u, r = i >> 3, c8 = i & 7;
            cpa16(ab + sw(r, c8), A + (size_t)(m0 + r) * DM + ko + c8 * 8);
            cpa16(bb + sw(r, c8), B + (size_t)(n0 + r) * DM + ko + c8 * 8);
        }
        CP_COMMIT();
    };

    float c[2][8][4];
    #pragma unroll
    for (int mt = 0; mt < 2; mt++)
        #pragma unroll
        for (int nt = 0; nt < 8; nt++)
            #pragma unroll
            for (int q = 0; q < 4; q++) c[mt][nt][q] = 0.f;

    issue(0, 0);
    issue(1, 64);

    for (int t = 0; t < 16; t++) {
        if (t == 15) { CP_WAIT(0); } else { CP_WAIT(1); }
        __syncthreads();
        if (t + 2 < 16) issue((t + 2) % 3, (t + 2) * 64);

        uint32_t ab = sb + (t % 3) * 32768;
        uint32_t bb = ab + 16384;
        #pragma unroll
        for (int ks8 = 0; ks8 < 8; ks8 += 2) {
            uint32_t a[2][4];
            #pragma unroll
            for (int mt = 0; mt < 2; mt++) {
                int row = wm * 32 + mt * 16 + (lane & 15);
                ldsm4(a[mt][0], a[mt][1], a[mt][2], a[mt][3],
                      ab + sw(row, ks8 + (lane >> 4)));
            }
            uint32_t b[4][4];
            #pragma unroll
            for (int g = 0; g < 4; g++) {
                int row = wn * 64 + g * 16 + ((lane >> 4) << 3) + (lane & 7);
                ldsm4(b[g][0], b[g][1], b[g][2], b[g][3],
                      bb + sw(row, ks8 + ((lane >> 3) & 1)));
            }
            #pragma unroll
            for (int mt = 0; mt < 2; mt++)
                #pragma unroll
                for (int nt = 0; nt < 8; nt++)
                    mma16816(c[mt][nt], a[mt], &b[nt >> 1][(nt & 1) * 2]);
        }
    }

    // ---------------- epilogue ----------------
    if (mode == 2) {
        float* out = (float*)outp;
        #pragma unroll
        for (int mt = 0; mt < 2; mt++) {
            int r = m0 + wm * 32 + mt * 16 + (lane >> 2);
            #pragma unroll
            for (int rh = 0; rh < 2; rh++) {
                int rr = r + 8 * rh;
                #pragma unroll
                for (int nt = 0; nt < 8; nt++) {
                    int n = nb + nt * 8 + 2 * (lane & 3);
                    float2 v;
                    v.x = c[mt][nt][rh * 2 + 0] + bias[n];
                    v.y = c[mt][nt][rh * 2 + 1] + bias[n + 1];
                    *(float2*)(out + (size_t)rr * DM + n) = v;
                }
            }
        }
        return;
    }

    __half* out = (__half*)outp;
    const int head = nb >> 6;
    #pragma unroll
    for (int mt = 0; mt < 2; mt++) {
        int r = m0 + wm * 32 + mt * 16 + (lane >> 2);
        #pragma unroll
        for (int rh = 0; rh < 2; rh++) {
            int rr = r + 8 * rh;
            int l = rr & (SL - 1), b_ = rr >> 11;
            __half* op = out + (((size_t)(b_ * NH + head)) * SL + l) * HD;
            #pragma unroll
            for (int nt = 0; nt < 4; nt++) {
                int d = nt * 8 + 2 * (lane & 3);
                float va0 = c[mt][nt][rh * 2 + 0]     + bias[nb + d];
                float va1 = c[mt][nt][rh * 2 + 1]     + bias[nb + d + 1];
                float vb0 = c[mt][nt + 4][rh * 2 + 0] + bias[nb + d + 32];
                float vb1 = c[mt][nt + 4][rh * 2 + 1] + bias[nb + d + 33];
                if (mode == 1) {
                    float2 cs = *(const float2*)&g_cos[l * 32 + d];
                    float2 sn = *(const float2*)&g_sin[l * 32 + d];
                    float t0 = va0 * cs.x - vb0 * sn.x;
                    float t1 = va1 * cs.y - vb1 * sn.y;
                    vb0 = (vb0 * cs.x + va0 * sn.x) * postscale;
                    vb1 = (vb1 * cs.y + va1 * sn.y) * postscale;
                    va0 = t0 * postscale; va1 = t1 * postscale;
                }
                *(uint32_t*)(op + d)      = pack_h2(va0, va1);
                *(uint32_t*)(op + d + 32) = pack_h2(vb0, vb1);
            }
        }
    }
}

// Merged Q/K/V projection: blockIdx.z selects operand set. Q gets log2e/8 prescale.
__global__ __launch_bounds__(256)
void gemm_qkv(const __half* __restrict__ A,
              const __half* __restrict__ Bq, const __half* __restrict__ Bk,
              const __half* __restrict__ Bv,
              const float* __restrict__ bq, const float* __restrict__ bk,
              const float* __restrict__ bv,
              __half* __restrict__ oq, __half* __restrict__ ok, __half* __restrict__ ov)
{
    extern __shared__ __align__(16) char smg[];
    const int z = blockIdx.z;
    const __half* B  = (z == 0) ? Bq : (z == 1) ? Bk : Bv;
    const float* bias = (z == 0) ? bq : (z == 1) ? bk : bv;
    __half* out = (z == 0) ? oq : (z == 1) ? ok : ov;
    gemm_body(A, B, bias, out, (z < 2) ? 1 : 0, (z == 0) ? QSCALE : 1.0f,
              saddr(smg), blockIdx.y * 128, blockIdx.x * 128);
}

// Output projection (fp32 out)
__global__ __launch_bounds__(256)
void gemm_o(const __half* __restrict__ A, const __half* __restrict__ B,
            const float* __restrict__ bias, float* __restrict__ out)
{
    extern __shared__ __align__(16) char smg[];
    gemm_body(A, B, bias, out, 2, 1.0f, saddr(smg), blockIdx.y * 128, blockIdx.x * 128);
}

// ============================================================================
// Flash attention: CTA = 128 queries of one (b,h), 4 warps, warp = 32 q-rows.
// NEW: PV + row sums accumulate in fp16 WITHIN each 128-key tile (2x mma rate;
// short 8-step sums, values <~200, safe in fp16), folded into fp32 cross-tile
// accumulators once per tile (cvt+add on fma pipe, overlaps tensor).
// dyn smem: Qs 16K + 2 * 32K = 81920 B.
// ============================================================================
__global__ __launch_bounds__(128)
void attn16(const __half* __restrict__ Q, const __half* __restrict__ K,
            const __half* __restrict__ V, __half* __restrict__ Ob)
{
    extern __shared__ __align__(16) char sma[];
    const uint32_t sb = saddr(sma);       // Qs at +0, stages at +16384
    const int tid = threadIdx.x, lane = tid & 31, warp = tid >> 5;  // warp 0..3
    const int bh = blockIdx.y, q0 = blockIdx.x << 7;
    const __half* Qg = Q + (size_t)bh * SL * HD;
    const __half* Kg = K + (size_t)bh * SL * HD;
    const __half* Vg = V + (size_t)bh * SL * HD;

    auto issueKV = [&](int st, int t) {
        uint32_t kb = sb + 16384 + st * 32768;
        uint32_t vb = kb + 16384;
        #pragma unroll
        for (int u = 0; u < 8; u++) {
            int i = tid + 128 * u, r = i >> 3, c8 = i & 7;
            cpa16(kb + sw(r, c8), Kg + (size_t)(t * 128 + r) * HD + c8 * 8);
            cpa16(vb + sw(r, c8), Vg + (size_t)(t * 128 + r) * HD + c8 * 8);
        }
        CP_COMMIT();
    };

    // Q tile + first KV stage
    #pragma unroll
    for (int u = 0; u < 8; u++) {
        int i = tid + 128 * u, r = i >> 3, c8 = i & 7;
        cpa16(sb + sw(r, c8), Qg + (size_t)(q0 + r) * HD + c8 * 8);
    }
    CP_COMMIT();
    issueKV(0, 0);
    CP_WAIT(0);
    __syncthreads();

    // persistent Q fragments: warp owns rows [warp*32, warp*32+32), 2 m-tiles
    uint32_t qa[2][4][4];
    #pragma unroll
    for (int mt = 0; mt < 2; mt++)
        #pragma unroll
        for (int ks = 0; ks < 4; ks++) {
            int row = warp * 32 + mt * 16 + (lane & 15);
            ldsm4(qa[mt][ks][0], qa[mt][ks][1], qa[mt][ks][2], qa[mt][ks][3],
                  sb + sw(row, 2 * ks + (lane >> 4)));
        }

    float o[2][8][4];
    #pragma unroll
    for (int mt = 0; mt < 2; mt++)
        #pragma unroll
        for (int dt = 0; dt < 8; dt++)
            #pragma unroll
            for (int q = 0; q < 4; q++) o[mt][dt][q] = 0.f;
    float rsum[2][4] = {{0.f,0.f,0.f,0.f},{0.f,0.f,0.f,0.f}};
    const uint32_t ones_b[2] = {0x3C003C00u, 0x3C003C00u};  // fp16 1.0 x4

    for (int t = 0; t < 16; t++) {
        if (t) { CP_WAIT(0); __syncthreads(); }
        if (t + 1 < 16) issueKV((t + 1) & 1, t + 1);

        uint32_t kbase = sb + 16384 + (t & 1) * 32768;
        uint32_t vbase = kbase + 16384;

        // S = Q @ K^T, fp16 accumulate; each kb fragment feeds BOTH m-tiles.
        uint32_t sh[2][16][2];
        #pragma unroll
        for (int mt = 0; mt < 2; mt++)
            #pragma unroll
            for (int nt = 0; nt < 16; nt++) { sh[mt][nt][0] = 0u; sh[mt][nt][1] = 0u; }
        #pragma unroll
        for (int ks = 0; ks < 4; ks++) {
            uint32_t kb[8][4];
            #pragma unroll
            for (int g = 0; g < 8; g++) {
                int row = g * 16 + ((lane >> 4) << 3) + (lane & 7);
                ldsm4(kb[g][0], kb[g][1], kb[g][2], kb[g][3],
                      kbase + sw(row, 2 * ks + ((lane >> 3) & 1)));
            }
            #pragma unroll
            for (int mt = 0; mt < 2; mt++)
                #pragma unroll
                for (int nt = 0; nt < 16; nt++)
                    mma16816h(sh[mt][nt], qa[mt][ks], &kb[nt >> 1][(nt & 1) * 2]);
        }

        // PV loop, fp16 per-tile accumulators (2x mma rate).
        uint32_t oh[2][8][2];
        uint32_t rh[2][2];
        #pragma unroll
        for (int mt = 0; mt < 2; mt++) {
            rh[mt][0] = 0u; rh[mt][1] = 0u;
            #pragma unroll
            for (int dt = 0; dt < 8; dt++) { oh[mt][dt][0] = 0u; oh[mt][dt][1] = 0u; }
        }
        #pragma unroll
        for (int kk = 0; kk < 8; kk++) {
            uint32_t vb[4][4];
            #pragma unroll
            for (int g = 0; g < 4; g++) {
                int row = kk * 16 + (((lane >> 3) & 1) << 3) + (lane & 7);
                ldsm4t(vb[g][0], vb[g][1], vb[g][2], vb[g][3],
                       vbase + sw(row, 2 * g + (lane >> 4)));
            }
            #pragma unroll
            for (int mt = 0; mt < 2; mt++) {
                uint32_t pa[4];
                pa[0] = exp2_h2r(sh[mt][2 * kk][0]);
                pa[1] = exp2_h2r(sh[mt][2 * kk][1]);
                pa[2] = exp2_h2r(sh[mt][2 * kk + 1][0]);
                pa[3] = exp2_h2r(sh[mt][2 * kk + 1][1]);
                #pragma unroll
                for (int dt = 0; dt < 8; dt++)
                    mma16816h(oh[mt][dt], pa, &vb[dt >> 1][(dt & 1) * 2]);
                mma16816h(rh[mt], pa, ones_b);
            }
        }
        // fold per-tile fp16 sums into fp32 accumulators
        #pragma unroll
        for (int mt = 0; mt < 2; mt++) {
            #pragma unroll
            for (int dt = 0; dt < 8; dt++) {
                float2 lo = __half22float2(*(__half2*)&oh[mt][dt][0]);
                float2 hi = __half22float2(*(__half2*)&oh[mt][dt][1]);
                o[mt][dt][0] += lo.x; o[mt][dt][1] += lo.y;
                o[mt][dt][2] += hi.x; o[mt][dt][3] += hi.y;
            }
            float2 rlo = __half22float2(*(__half2*)&rh[mt][0]);
            float2 rhi = __half22float2(*(__half2*)&rh[mt][1]);
            rsum[mt][0] += rlo.x;   // col parity 0 of rows r / r+8 hold the sums
            rsum[mt][2] += rhi.x;
        }
    }

    // epilogue: normalize, write fp16 [B,L,D]
    const int b_ = bh >> 4, h = bh & 15;
    #pragma unroll
    for (int mt = 0; mt < 2; mt++) {
        const int r = warp * 32 + mt * 16 + (lane >> 2);
        const float inv0 = 1.f / rsum[mt][0], inv1 = 1.f / rsum[mt][2];
        __half* op0 = Ob + ((size_t)(b_ * SL + q0 + r)) * DM + h * HD;
        __half* op1 = Ob + ((size_t)(b_ * SL + q0 + r + 8)) * DM + h * HD;
        #pragma unroll
        for (int dt = 0; dt < 8; dt++) {
            int d = dt * 8 + 2 * (lane & 3);
            *(uint32_t*)(op0 + d) = pack_h2(o[mt][dt][0] * inv0, o[mt][dt][1] * inv0);
            *(uint32_t*)(op1 + d) = pack_h2(o[mt][dt][2] * inv1, o[mt][dt][3] * inv1);
        }
    }
}

extern "C" void kernel_launch(void* const* d_in, const int* in_sizes, int n_in,
                              void* d_out, int out_size)
{
    (void)in_sizes; (void)n_in; (void)out_size;
    const float* x  = (const float*)d_in[0];
    const float* Wq = (const float*)d_in[1];
    const float* bq = (const float*)d_in[2];
    const float* Wk = (const float*)d_in[3];
    const float* bk = (const float*)d_in[4];
    const float* Wv = (const float*)d_in[5];
    const float* bv = (const float*)d_in[6];
    const float* Wo = (const float*)d_in[7];
    const float* bo = (const float*)d_in[8];
    float* out = (float*)d_out;

    __half *xh, *wqh, *wkh, *wvh, *woh, *qh, *kh, *vh, *ah;
    cudaGetSymbolAddress((void**)&xh,  g_xh);
    cudaGetSymbolAddress((void**)&wqh, g_wqh);
    cudaGetSymbolAddress((void**)&wkh, g_wkh);
    cudaGetSymbolAddress((void**)&wvh, g_wvh);
    cudaGetSymbolAddress((void**)&woh, g_woh);
    cudaGetSymbolAddress((void**)&qh,  g_qh);
    cudaGetSymbolAddress((void**)&kh,  g_kh);
    cudaGetSymbolAddress((void**)&vh,  g_vh);
    cudaGetSymbolAddress((void**)&ah,  g_ah);

    const int shm_g = 3 * 32768;            // 98304
    const int shm_a = 16384 + 2 * 32768;    // 81920
    static int configured = 0;
    if (!configured) {
        cudaFuncSetAttribute(gemm_qkv, cudaFuncAttributeMaxDynamicSharedMemorySize, shm_g);
        cudaFuncSetAttribute(gemm_o,   cudaFuncAttributeMaxDynamicSharedMemorySize, shm_g);
        cudaFuncSetAttribute(attn16,   cudaFuncAttributeMaxDynamicSharedMemorySize, shm_a);
        configured = 1;
    }

    prepass<<<2112, 256>>>(x, Wq, Wk, Wv, Wo);

    gemm_qkv<<<dim3(DM / 128, MT / 128, 3), 256, shm_g>>>(
        xh, wqh, wkh, wvh, bq, bk, bv, qh, kh, vh);

    attn16<<<dim3(SL / 128, NB * NH), 128, shm_a>>>(qh, kh, vh, ah);

    gemm_o<<<dim3(DM / 128, MT / 128), 256, shm_g>>>(ah, woh, bo, out);
}

// round 17
// speedup vs baseline: 1.0186x; 1.0186x over previous
#include <cuda_runtime.h>
#include <cuda_fp16.h>
#include <math.h>
#include <stdint.h>

#define DM   1024
#define NH   16
#define HD   64
#define NB   2
#define SL   2048
#define MT   (NB*SL)   // 4096

// fp16 scratch (device globals: allocation-free)
__device__ __align__(16) __half g_xh[MT*DM];
__device__ __align__(16) __half g_wqh[DM*DM];
__device__ __align__(16) __half g_wkh[DM*DM];
__device__ __align__(16) __half g_wvh[DM*DM];
__device__ __align__(16) __half g_woh[DM*DM];
__device__ __align__(16) __half g_qh[NB*NH*SL*HD];   // [B][H][L][Dh], pre-scaled by log2e/8
__device__ __align__(16) __half g_kh[NB*NH*SL*HD];
__device__ __align__(16) __half g_vh[NB*NH*SL*HD];
__device__ __align__(16) __half g_ah[MT*DM];         // attn out [B,L,D]
__device__ float g_cos[SL*32];
__device__ float g_sin[SL*32];

// ---------------- helpers ----------------
__device__ __forceinline__ uint32_t saddr(const void* p) {
    return (uint32_t)__cvta_generic_to_shared(p);
}
__device__ __forceinline__ void ldsm4(uint32_t& r0, uint32_t& r1, uint32_t& r2, uint32_t& r3, uint32_t a) {
    asm volatile("ldmatrix.sync.aligned.m8n8.x4.shared.b16 {%0,%1,%2,%3}, [%4];"
        : "=r"(r0), "=r"(r1), "=r"(r2), "=r"(r3) : "r"(a));
}
__device__ __forceinline__ void ldsm4t(uint32_t& r0, uint32_t& r1, uint32_t& r2, uint32_t& r3, uint32_t a) {
    asm volatile("ldmatrix.sync.aligned.m8n8.x4.trans.shared.b16 {%0,%1,%2,%3}, [%4];"
        : "=r"(r0), "=r"(r1), "=r"(r2), "=r"(r3) : "r"(a));
}
__device__ __forceinline__ void mma16816(float* c, const uint32_t* a, const uint32_t* b) {
    asm volatile("mma.sync.aligned.m16n8k16.row.col.f32.f16.f16.f32 "
        "{%0,%1,%2,%3}, {%4,%5,%6,%7}, {%8,%9}, {%0,%1,%2,%3};"
        : "+f"(c[0]), "+f"(c[1]), "+f"(c[2]), "+f"(c[3])
        : "r"(a[0]), "r"(a[1]), "r"(a[2]), "r"(a[3]), "r"(b[0]), "r"(b[1]));
}
// fp16-accumulate variant (2x rate): C/D are 2 regs of f16x2.
__device__ __forceinline__ void mma16816h(uint32_t* c, const uint32_t* a, const uint32_t* b) {
    asm volatile("mma.sync.aligned.m16n8k16.row.col.f16.f16.f16.f16 "
        "{%0,%1}, {%2,%3,%4,%5}, {%6,%7}, {%0,%1};"
        : "+r"(c[0]), "+r"(c[1])
        : "r"(a[0]), "r"(a[1]), "r"(a[2]), "r"(a[3]), "r"(b[0]), "r"(b[1]));
}
__device__ __forceinline__ uint32_t pack_h2(float a, float b) {
    __half2 h = __floats2half2_rn(a, b);
    return *reinterpret_cast<uint32_t*>(&h);
}
// ex2 on an f16x2 register (log2-domain -> probabilities), one MUFU for 2 elems
__device__ __forceinline__ uint32_t exp2_h2r(uint32_t p) {
    uint32_t r;
    asm volatile("ex2.approx.f16x2 %0, %1;" : "=r"(r) : "r"(p));
    return r;
}
__device__ __forceinline__ void cpa16(uint32_t dst, const void* src) {
    asm volatile("cp.async.cg.shared.global [%0], [%1], 16;" :: "r"(dst), "l"(src));
}
#define CP_COMMIT() asm volatile("cp.async.commit_group;")
#define CP_WAIT(n)  asm volatile("cp.async.wait_group %0;" :: "n"(n))

// XOR-swizzled byte offset inside a [rows][64 halves] tile (128B row pitch)
__device__ __forceinline__ uint32_t sw(int r, int c8) {
    return (uint32_t)(r * 128 + ((c8 ^ (r & 7)) << 4));
}

#define QSCALE 0.18033688011112042f   // log2(e)/8

// ---------------- merged prepass: 5x f2h + rope table, one launch ----------
__global__ __launch_bounds__(256)
void prepass(const float* __restrict__ x,
             const float* __restrict__ Wq, const float* __restrict__ Wk,
             const float* __restrict__ Wv, const float* __restrict__ Wo)
{
    int b = blockIdx.x;
    if (b >= 2048) {   // rope: 65536 elems, 64 blocks x 256 thr x 4
        int i0 = (b - 2048) * 1024 + threadIdx.x;
        #pragma unroll
        for (int u = 0; u < 4; u++) {
            int i = i0 + u * 256;
            int l = i >> 5, j = i & 31;
            float inv = (float)exp((double)j * -0.28782313662425572);  // 10000^(-j/32)
            float ang = (float)l * inv;
            float s, c;
            sincosf(ang, &s, &c);
            g_cos[i] = c;
            g_sin[i] = s;
        }
        return;
    }
    const float* src;
    __half* dst;
    int base;
    if      (b < 1024) { src = x;  dst = g_xh;  base = 0;    }
    else if (b < 1280) { src = Wq; dst = g_wqh; base = 1024; }
    else if (b < 1536) { src = Wk; dst = g_wkh; base = 1280; }
    else if (b < 1792) { src = Wv; dst = g_wvh; base = 1536; }
    else               { src = Wo; dst = g_woh; base = 1792; }
    int i0 = (b - base) * 1024 + threadIdx.x;
    #pragma unroll
    for (int u = 0; u < 4; u++) {
        int i = i0 + u * 256;
        float4 v = ((const float4*)src)[i];
        uint2 h;
        h.x = pack_h2(v.x, v.y);
        h.y = pack_h2(v.z, v.w);
        ((uint2*)dst)[i] = h;
    }
}

// ============================================================================
// GEMM body (fp16 in): out[m,n] = sum_k A[m,k]*B[n,k] + bias[n].
// CTA 128x128, 8 warps (4m x 2n), k-slice 64, 3-stage cp.async pipeline.
// (Round-13 shape, unchanged.)
// ============================================================================
__device__ __forceinline__
void gemm_body(const __half* __restrict__ A, const __half* __restrict__ B,
               const float* __restrict__ bias, void* __restrict__ outp,
               int mode, float postscale, uint32_t sb, int m0, int n0)
{
    const int tid = threadIdx.x, lane = tid & 31, warp = tid >> 5;
    const int wm = warp >> 1, wn = warp & 1;
    const int nb = n0 + wn * 64;

    auto issue = [&](int st, int ko) {
        uint32_t ab = sb + st * 32768;
        uint32_t bb = ab + 16384;
        #pragma unroll
        for (int u = 0; u < 4; u++) {
            int i = tid + 256 * u, r = i >> 3, c8 = i & 7;
            cpa16(ab + sw(r, c8), A + (size_t)(m0 + r) * DM + ko + c8 * 8);
            cpa16(bb + sw(r, c8), B + (size_t)(n0 + r) * DM + ko + c8 * 8);
        }
        CP_COMMIT();
    };

    float c[2][8][4];
    #pragma unroll
    for (int mt = 0; mt < 2; mt++)
        #pragma unroll
        for (int nt = 0; nt < 8; nt++)
            #pragma unroll
            for (int q = 0; q < 4; q++) c[mt][nt][q] = 0.f;

    issue(0, 0);
    issue(1, 64);

    for (int t = 0; t < 16; t++) {
        if (t == 15) { CP_WAIT(0); } else { CP_WAIT(1); }
        __syncthreads();
        if (t + 2 < 16) issue((t + 2) % 3, (t + 2) * 64);

        uint32_t ab = sb + (t % 3) * 32768;
        uint32_t bb = ab + 16384;
        #pragma unroll
        for (int ks8 = 0; ks8 < 8; ks8 += 2) {
            uint32_t a[2][4];
            #pragma unroll
            for (int mt = 0; mt < 2; mt++) {
                int row = wm * 32 + mt * 16 + (lane & 15);
                ldsm4(a[mt][0], a[mt][1], a[mt][2], a[mt][3],
                      ab + sw(row, ks8 + (lane >> 4)));
            }
            uint32_t b[4][4];
            #pragma unroll
            for (int g = 0; g < 4; g++) {
                int row = wn * 64 + g * 16 + ((lane >> 4) << 3) + (lane & 7);
                ldsm4(b[g][0], b[g][1], b[g][2], b[g][3],
                      bb + sw(row, ks8 + ((lane >> 3) & 1)));
            }
            #pragma unroll
            for (int mt = 0; mt < 2; mt++)
                #pragma unroll
                for (int nt = 0; nt < 8; nt++)
                    mma16816(c[mt][nt], a[mt], &b[nt >> 1][(nt & 1) * 2]);
        }
    }

    // ---------------- epilogue ----------------
    if (mode == 2) {
        float* out = (float*)outp;
        #pragma unroll
        for (int mt = 0; mt < 2; mt++) {
            int r = m0 + wm * 32 + mt * 16 + (lane >> 2);
            #pragma unroll
            for (int rh = 0; rh < 2; rh++) {
                int rr = r + 8 * rh;
                #pragma unroll
                for (int nt = 0; nt < 8; nt++) {
                    int n = nb + nt * 8 + 2 * (lane & 3);
                    float2 v;
                    v.x = c[mt][nt][rh * 2 + 0] + bias[n];
                    v.y = c[mt][nt][rh * 2 + 1] + bias[n + 1];
                    *(float2*)(out + (size_t)rr * DM + n) = v;
                }
            }
        }
        return;
    }

    __half* out = (__half*)outp;
    const int head = nb >> 6;
    #pragma unroll
    for (int mt = 0; mt < 2; mt++) {
        int r = m0 + wm * 32 + mt * 16 + (lane >> 2);
        #pragma unroll
        for (int rh = 0; rh < 2; rh++) {
            int rr = r + 8 * rh;
            int l = rr & (SL - 1), b_ = rr >> 11;
            __half* op = out + (((size_t)(b_ * NH + head)) * SL + l) * HD;
            #pragma unroll
            for (int nt = 0; nt < 4; nt++) {
                int d = nt * 8 + 2 * (lane & 3);
                float va0 = c[mt][nt][rh * 2 + 0]     + bias[nb + d];
                float va1 = c[mt][nt][rh * 2 + 1]     + bias[nb + d + 1];
                float vb0 = c[mt][nt + 4][rh * 2 + 0] + bias[nb + d + 32];
                float vb1 = c[mt][nt + 4][rh * 2 + 1] + bias[nb + d + 33];
                if (mode == 1) {
                    float2 cs = *(const float2*)&g_cos[l * 32 + d];
                    float2 sn = *(const float2*)&g_sin[l * 32 + d];
                    float t0 = va0 * cs.x - vb0 * sn.x;
                    float t1 = va1 * cs.y - vb1 * sn.y;
                    vb0 = (vb0 * cs.x + va0 * sn.x) * postscale;
                    vb1 = (vb1 * cs.y + va1 * sn.y) * postscale;
                    va0 = t0 * postscale; va1 = t1 * postscale;
                }
                *(uint32_t*)(op + d)      = pack_h2(va0, va1);
                *(uint32_t*)(op + d + 32) = pack_h2(vb0, vb1);
            }
        }
    }
}

// Merged Q/K/V projection: blockIdx.z selects operand set. Q gets log2e/8 prescale.
__global__ __launch_bounds__(256)
void gemm_qkv(const __half* __restrict__ A,
              const __half* __restrict__ Bq, const __half* __restrict__ Bk,
              const __half* __restrict__ Bv,
              const float* __restrict__ bq, const float* __restrict__ bk,
              const float* __restrict__ bv,
              __half* __restrict__ oq, __half* __restrict__ ok, __half* __restrict__ ov)
{
    extern __shared__ __align__(16) char smg[];
    const int z = blockIdx.z;
    const __half* B  = (z == 0) ? Bq : (z == 1) ? Bk : Bv;
    const float* bias = (z == 0) ? bq : (z == 1) ? bk : bv;
    __half* out = (z == 0) ? oq : (z == 1) ? ok : ov;
    gemm_body(A, B, bias, out, (z < 2) ? 1 : 0, (z == 0) ? QSCALE : 1.0f,
              saddr(smg), blockIdx.y * 128, blockIdx.x * 128);
}

// Output projection (fp32 out)
__global__ __launch_bounds__(256)
void gemm_o(const __half* __restrict__ A, const __half* __restrict__ B,
            const float* __restrict__ bias, float* __restrict__ out)
{
    extern __shared__ __align__(16) char smg[];
    gemm_body(A, B, bias, out, 2, 1.0f, saddr(smg), blockIdx.y * 128, blockIdx.x * 128);
}

// ============================================================================
// Flash attention: CTA = 128 queries of one (b,h), 4 warps, warp = 32 q-rows.
// Round-13 MATH exactly (S fp16-acc, PV/rsum fp32-acc, per-kk ex2) but:
//  - Q parked in stage1's V region (dead after qa fragment extraction)
//    -> smem 65536 B -> 3 CTAs/SM (latency-bound kernel needs the warps)
//  - per-tile work split into two nt-halves -> sh/kb live regs halved,
//    fits the 170-reg budget of __launch_bounds__(128, 3).
// Same mma ops in same per-accumulator order -> bitwise-identical results.
// ============================================================================
__global__ __launch_bounds__(128, 3)
void attn16(const __half* __restrict__ Q, const __half* __restrict__ K,
            const __half* __restrict__ V, __half* __restrict__ Ob)
{
    extern __shared__ __align__(16) char sma[];
    const uint32_t sb = saddr(sma);       // stage0 @0 (K,V), stage1 @32768 (K,V)
    const uint32_t qpark = sb + 49152;    // Q parked in stage1's V slot
    const int tid = threadIdx.x, lane = tid & 31, warp = tid >> 5;  // warp 0..3
    const int bh = blockIdx.y, q0 = blockIdx.x << 7;
    const __half* Qg = Q + (size_t)bh * SL * HD;
    const __half* Kg = K + (size_t)bh * SL * HD;
    const __half* Vg = V + (size_t)bh * SL * HD;

    auto issueKV = [&](int st, int t) {
        uint32_t kb = sb + st * 32768;
        uint32_t vb = kb + 16384;
        #pragma unroll
        for (int u = 0; u < 8; u++) {
            int i = tid + 128 * u, r = i >> 3, c8 = i & 7;
            cpa16(kb + sw(r, c8), Kg + (size_t)(t * 128 + r) * HD + c8 * 8);
            cpa16(vb + sw(r, c8), Vg + (size_t)(t * 128 + r) * HD + c8 * 8);
        }
        CP_COMMIT();
    };

    // Q tile (into parked region) + first KV stage (stage0)
    #pragma unroll
    for (int u = 0; u < 8; u++) {
        int i = tid + 128 * u, r = i >> 3, c8 = i & 7;
        cpa16(qpark + sw(r, c8), Qg + (size_t)(q0 + r) * HD + c8 * 8);
    }
    CP_COMMIT();
    issueKV(0, 0);
    CP_WAIT(0);
    __syncthreads();

    // persistent Q fragments: warp owns rows [warp*32, warp*32+32), 2 m-tiles
    uint32_t qa[2][4][4];
    #pragma unroll
    for (int mt = 0; mt < 2; mt++)
        #pragma unroll
        for (int ks = 0; ks < 4; ks++) {
            int row = warp * 32 + mt * 16 + (lane & 15);
            ldsm4(qa[mt][ks][0], qa[mt][ks][1], qa[mt][ks][2], qa[mt][ks][3],
                  qpark + sw(row, 2 * ks + (lane >> 4)));
        }
    __syncthreads();   // all warps done reading Q before stage1 gets overwritten

    float o[2][8][4];
    #pragma unroll
    for (int mt = 0; mt < 2; mt++)
        #pragma unroll
        for (int dt = 0; dt < 8; dt++)
            #pragma unroll
            for (int q = 0; q < 4; q++) o[mt][dt][q] = 0.f;
    float rsum[2][4] = {{0.f,0.f,0.f,0.f},{0.f,0.f,0.f,0.f}};
    const uint32_t ones_b[2] = {0x3C003C00u, 0x3C003C00u};  // fp16 1.0 x4

    for (int t = 0; t < 16; t++) {
        if (t) { CP_WAIT(0); __syncthreads(); }
        if (t + 1 < 16) issueKV((t + 1) & 1, t + 1);

        uint32_t kbase = sb + (t & 1) * 32768;
        uint32_t vbase = kbase + 16384;

        // two nt-halves: keys [half*64, half*64+64)
        #pragma unroll
        for (int half = 0; half < 2; half++) {
            // S = Q @ K^T over this half's 64 keys, fp16 accumulate
            uint32_t sh[2][8][2];
            #pragma unroll
            for (int mt = 0; mt < 2; mt++)
                #pragma unroll
                for (int n8 = 0; n8 < 8; n8++) { sh[mt][n8][0] = 0u; sh[mt][n8][1] = 0u; }
            #pragma unroll
            for (int ks = 0; ks < 4; ks++) {
                uint32_t kb[4][4];
                #pragma unroll
                for (int g = 0; g < 4; g++) {
                    int row = (half * 4 + g) * 16 + ((lane >> 4) << 3) + (lane & 7);
                    ldsm4(kb[g][0], kb[g][1], kb[g][2], kb[g][3],
                          kbase + sw(row, 2 * ks + ((lane >> 3) & 1)));
                }
                #pragma unroll
                for (int mt = 0; mt < 2; mt++)
                    #pragma unroll
                    for (int n8 = 0; n8 < 8; n8++)
                        mma16816h(sh[mt][n8], qa[mt][ks], &kb[n8 >> 1][(n8 & 1) * 2]);
            }

            // PV over this half's 4 kk groups (fp32 accumulate, as round 13)
            #pragma unroll
            for (int kkl = 0; kkl < 4; kkl++) {
                int kk = half * 4 + kkl;
                uint32_t vb[4][4];
                #pragma unroll
                for (int g = 0; g < 4; g++) {
                    int row = kk * 16 + (((lane >> 3) & 1) << 3) + (lane & 7);
                    ldsm4t(vb[g][0], vb[g][1], vb[g][2], vb[g][3],
                           vbase + sw(row, 2 * g + (lane >> 4)));
                }
                #pragma unroll
                for (int mt = 0; mt < 2; mt++) {
                    uint32_t pa[4];
                    pa[0] = exp2_h2r(sh[mt][2 * kkl][0]);
                    pa[1] = exp2_h2r(sh[mt][2 * kkl][1]);
                    pa[2] = exp2_h2r(sh[mt][2 * kkl + 1][0]);
                    pa[3] = exp2_h2r(sh[mt][2 * kkl + 1][1]);
                    #pragma unroll
                    for (int dt = 0; dt < 8; dt++)
                        mma16816(o[mt][dt], pa, &vb[dt >> 1][(dt & 1) * 2]);
                    mma16816(rsum[mt], pa, ones_b);
                }
            }
        }
    }

    // epilogue: normalize, write fp16 [B,L,D]
    const int b_ = bh >> 4, h = bh & 15;
    #pragma unroll
    for (int mt = 0; mt < 2; mt++) {
        const int r = warp * 32 + mt * 16 + (lane >> 2);
        const float inv0 = 1.f / rsum[mt][0], inv1 = 1.f / rsum[mt][2];
        __half* op0 = Ob + ((size_t)(b_ * SL + q0 + r)) * DM + h * HD;
        __half* op1 = Ob + ((size_t)(b_ * SL + q0 + r + 8)) * DM + h * HD;
        #pragma unroll
        for (int dt = 0; dt < 8; dt++) {
            int d = dt * 8 + 2 * (lane & 3);
            *(uint32_t*)(op0 + d) = pack_h2(o[mt][dt][0] * inv0, o[mt][dt][1] * inv0);
            *(uint32_t*)(op1 + d) = pack_h2(o[mt][dt][2] * inv1, o[mt][dt][3] * inv1);
        }
    }
}

extern "C" void kernel_launch(void* const* d_in, const int* in_sizes, int n_in,
                              void* d_out, int out_size)
{
    (void)in_sizes; (void)n_in; (void)out_size;
    const float* x  = (const float*)d_in[0];
    const float* Wq = (const float*)d_in[1];
    const float* bq = (const float*)d_in[2];
    const float* Wk = (const float*)d_in[3];
    const float* bk = (const float*)d_in[4];
    const float* Wv = (const float*)d_in[5];
    const float* bv = (const float*)d_in[6];
    const float* Wo = (const float*)d_in[7];
    const float* bo = (const float*)d_in[8];
    float* out = (float*)d_out;

    __half *xh, *wqh, *wkh, *wvh, *woh, *qh, *kh, *vh, *ah;
    cudaGetSymbolAddress((void**)&xh,  g_xh);
    cudaGetSymbolAddress((void**)&wqh, g_wqh);
    cudaGetSymbolAddress((void**)&wkh, g_wkh);
    cudaGetSymbolAddress((void**)&wvh, g_wvh);
    cudaGetSymbolAddress((void**)&woh, g_woh);
    cudaGetSymbolAddress((void**)&qh,  g_qh);
    cudaGetSymbolAddress((void**)&kh,  g_kh);
    cudaGetSymbolAddress((void**)&vh,  g_vh);
    cudaGetSymbolAddress((void**)&ah,  g_ah);

    const int shm_g = 3 * 32768;   // 98304
    const int shm_a = 65536;       // 2 KV stages; Q parked inside stage1
    static int configured = 0;
    if (!configured) {
        cudaFuncSetAttribute(gemm_qkv, cudaFuncAttributeMaxDynamicSharedMemorySize, shm_g);
        cudaFuncSetAttribute(gemm_o,   cudaFuncAttributeMaxDynamicSharedMemorySize, shm_g);
        cudaFuncSetAttribute(attn16,   cudaFuncAttributeMaxDynamicSharedMemorySize, shm_a);
        configured = 1;
    }

    prepass<<<2112, 256>>>(x, Wq, Wk, Wv, Wo);

    gemm_qkv<<<dim3(DM / 128, MT / 128, 3), 256, shm_g>>>(
        xh, wqh, wkh, wvh, bq, bk, bv, qh, kh, vh);

    attn16<<<dim3(SL / 128, NB * NH), 128, shm_a>>>(qh, kh, vh, ah);

    gemm_o<<<dim3(DM / 128, MT / 128), 256, shm_g>>>(ah, woh, bo, out);
}